// round 1
// baseline (speedup 1.0000x reference)
#include <cuda_runtime.h>
#include <cuda_bf16.h>
#include <cstdint>

// Problem constants
#define T_STEPS 500
#define BATCH   128
#define WIN     256
#define NF      512
#define NC      10
#define M_ROWS  (T_STEPS * BATCH)   // 64000
#define K3      (WIN * 3)           // 768  (extended-K bf16 split: [h,l,h] x [h,h,l])
#define CELLS   (BATCH * NF)        // 65536

// GEMM tiling
#define BM 128
#define BN 128
#define BK 32
#define NKITER (K3 / BK)            // 24
#define SKEW 8
#define LDS_ROW (BK + SKEW)         // 40 bf16 = 80B row stride (conflict-free for ldmatrix)

// -------- device scratch (static allocation is the sanctioned scratch path) --------
__device__ __nv_bfloat16 g_Xs[(size_t)M_ROWS * K3];   // ~98 MB
__device__ __nv_bfloat16 g_Ws[(size_t)NF * K3];       // ~0.8 MB
__device__ float         g_proj[(size_t)M_ROWS * NF]; // 131 MB
__device__ float         g_counts[CELLS];

// ---------------------------------------------------------------------------------
// Split fp32 -> (hi, lo) bf16, pack extended-K slots.
//   A (x_windows): per element k -> slots [h, l, h]
//   B (weights):   per element k -> slots [h, h, l]
// so slotwise products give h*h + l*h + h*l (lo*lo dropped, ~2^-20 negligible).
// ---------------------------------------------------------------------------------
__global__ void split_x_kernel(const float* __restrict__ x, int npairs) {
    int i = blockIdx.x * blockDim.x + threadIdx.x;
    if (i >= npairs) return;
    float2 v = reinterpret_cast<const float2*>(x)[i];
    __nv_bfloat16 h0 = __float2bfloat16(v.x);
    __nv_bfloat16 l0 = __float2bfloat16(v.x - __bfloat162float(h0));
    __nv_bfloat16 h1 = __float2bfloat16(v.y);
    __nv_bfloat16 l1 = __float2bfloat16(v.y - __bfloat162float(h1));
    unsigned hu0 = __bfloat16_as_ushort(h0), lu0 = __bfloat16_as_ushort(l0);
    unsigned hu1 = __bfloat16_as_ushort(h1), lu1 = __bfloat16_as_ushort(l1);
    // slots [6i..6i+5] = h0, l0, h0, h1, l1, h1
    unsigned* out = reinterpret_cast<unsigned*>(g_Xs);
    out[3 * i + 0] = hu0 | (lu0 << 16);
    out[3 * i + 1] = hu0 | (hu1 << 16);
    out[3 * i + 2] = lu1 | (hu1 << 16);
}

__global__ void split_w_kernel(const float* __restrict__ w, int npairs) {
    int i = blockIdx.x * blockDim.x + threadIdx.x;
    if (i >= npairs) return;
    float2 v = reinterpret_cast<const float2*>(w)[i];
    __nv_bfloat16 h0 = __float2bfloat16(v.x);
    __nv_bfloat16 l0 = __float2bfloat16(v.x - __bfloat162float(h0));
    __nv_bfloat16 h1 = __float2bfloat16(v.y);
    __nv_bfloat16 l1 = __float2bfloat16(v.y - __bfloat162float(h1));
    unsigned hu0 = __bfloat16_as_ushort(h0), lu0 = __bfloat16_as_ushort(l0);
    unsigned hu1 = __bfloat16_as_ushort(h1), lu1 = __bfloat16_as_ushort(l1);
    // slots [6i..6i+5] = h0, h0, l0, h1, h1, l1
    unsigned* out = reinterpret_cast<unsigned*>(g_Ws);
    out[3 * i + 0] = hu0 | (hu0 << 16);
    out[3 * i + 1] = lu0 | (hu1 << 16);
    out[3 * i + 2] = hu1 | (lu1 << 16);
}

// ---------------------------------------------------------------------------------
// GEMM: proj[M_ROWS, NF] (fp32) = Xs[M_ROWS, K3] * Ws[NF, K3]^T  via mma.sync bf16.
// CTA 128x128, 8 warps (4 m-wise x 2 n-wise), each warp 32x64. cp.async double-buffer.
// ---------------------------------------------------------------------------------
__global__ void __launch_bounds__(256) gemm_kernel() {
    __shared__ __align__(16) __nv_bfloat16 sA[2][BM * LDS_ROW];
    __shared__ __align__(16) __nv_bfloat16 sB[2][BN * LDS_ROW];

    const int tid  = threadIdx.x;
    const int bn   = blockIdx.x;     // 0..3
    const int bm   = blockIdx.y;     // 0..499
    const int warp = tid >> 5;
    const int lane = tid & 31;
    const int wm   = warp & 3;       // m offset = 32*wm
    const int wn   = warp >> 2;      // n offset = 64*wn

    float acc[2][8][4];
    #pragma unroll
    for (int mi = 0; mi < 2; mi++)
        #pragma unroll
        for (int n8 = 0; n8 < 8; n8++)
            #pragma unroll
            for (int q = 0; q < 4; q++) acc[mi][n8][q] = 0.f;

    auto load_stage = [&](int st, int kt) {
        #pragma unroll
        for (int it = 0; it < 2; it++) {
            int c = tid + it * 256;          // 0..511
            int r = c >> 2, q = c & 3;       // row, 16B-chunk within 64B k-slab
            const __nv_bfloat16* gA = &g_Xs[(size_t)(bm * BM + r) * K3 + kt * BK + q * 8];
            unsigned sa = (unsigned)__cvta_generic_to_shared(&sA[st][r * LDS_ROW + q * 8]);
            asm volatile("cp.async.cg.shared.global [%0], [%1], 16;\n" :: "r"(sa), "l"(gA));
            const __nv_bfloat16* gB = &g_Ws[(size_t)(bn * BN + r) * K3 + kt * BK + q * 8];
            unsigned sb = (unsigned)__cvta_generic_to_shared(&sB[st][r * LDS_ROW + q * 8]);
            asm volatile("cp.async.cg.shared.global [%0], [%1], 16;\n" :: "r"(sb), "l"(gB));
        }
    };

    auto compute_stage = [&](int st) {
        #pragma unroll
        for (int kk = 0; kk < BK; kk += 16) {
            unsigned af[2][4];
            #pragma unroll
            for (int mi = 0; mi < 2; mi++) {
                int row = wm * 32 + mi * 16 + (lane & 15);
                int col = kk + (lane >> 4) * 8;
                unsigned a = (unsigned)__cvta_generic_to_shared(&sA[st][row * LDS_ROW + col]);
                asm volatile("ldmatrix.sync.aligned.m8n8.x4.shared.b16 {%0,%1,%2,%3}, [%4];"
                             : "=r"(af[mi][0]), "=r"(af[mi][1]), "=r"(af[mi][2]), "=r"(af[mi][3])
                             : "r"(a));
            }
            unsigned bfr[4][4];
            #pragma unroll
            for (int nj = 0; nj < 4; nj++) {
                int row = wn * 64 + nj * 16 + (lane & 7) + ((lane >> 4) << 3);
                int col = kk + ((lane >> 3) & 1) * 8;
                unsigned a = (unsigned)__cvta_generic_to_shared(&sB[st][row * LDS_ROW + col]);
                asm volatile("ldmatrix.sync.aligned.m8n8.x4.shared.b16 {%0,%1,%2,%3}, [%4];"
                             : "=r"(bfr[nj][0]), "=r"(bfr[nj][1]), "=r"(bfr[nj][2]), "=r"(bfr[nj][3])
                             : "r"(a));
            }
            #pragma unroll
            for (int mi = 0; mi < 2; mi++) {
                #pragma unroll
                for (int n8 = 0; n8 < 8; n8++) {
                    int nj = n8 >> 1, h = (n8 & 1) * 2;
                    asm volatile(
                        "mma.sync.aligned.m16n8k16.row.col.f32.bf16.bf16.f32 "
                        "{%0,%1,%2,%3}, {%4,%5,%6,%7}, {%8,%9}, {%0,%1,%2,%3};"
                        : "+f"(acc[mi][n8][0]), "+f"(acc[mi][n8][1]),
                          "+f"(acc[mi][n8][2]), "+f"(acc[mi][n8][3])
                        : "r"(af[mi][0]), "r"(af[mi][1]), "r"(af[mi][2]), "r"(af[mi][3]),
                          "r"(bfr[nj][h]), "r"(bfr[nj][h + 1]));
                }
            }
        }
    };

    load_stage(0, 0);
    asm volatile("cp.async.commit_group;");
    for (int kt = 0; kt < NKITER; kt++) {
        if (kt + 1 < NKITER) {
            load_stage((kt + 1) & 1, kt + 1);
            asm volatile("cp.async.commit_group;");
            asm volatile("cp.async.wait_group 1;");
        } else {
            asm volatile("cp.async.wait_group 0;");
        }
        __syncthreads();
        compute_stage(kt & 1);
        __syncthreads();
    }

    // Epilogue: fp32 accumulators -> g_proj
    #pragma unroll
    for (int mi = 0; mi < 2; mi++) {
        #pragma unroll
        for (int n8 = 0; n8 < 8; n8++) {
            int grow = bm * BM + wm * 32 + mi * 16 + (lane >> 2);
            int gcol = bn * BN + wn * 64 + n8 * 8 + (lane & 3) * 2;
            float2* p0 = reinterpret_cast<float2*>(&g_proj[(size_t)grow * NF + gcol]);
            *p0 = make_float2(acc[mi][n8][0], acc[mi][n8][1]);
            float2* p1 = reinterpret_cast<float2*>(&g_proj[(size_t)(grow + 8) * NF + gcol]);
            *p1 = make_float2(acc[mi][n8][2], acc[mi][n8][3]);
        }
    }
}

// ---------------------------------------------------------------------------------
// LIF scan: one thread per (b, f) cell, sequential over T. Coalesced proj reads.
// ---------------------------------------------------------------------------------
__global__ void scan_kernel() {
    int cell = blockIdx.x * blockDim.x + threadIdx.x;
    float u = 0.f, tr = 0.f, cnt = 0.f;
    const float* p = g_proj + cell;

#define LIF_STEP(PV)                                     \
    do {                                                 \
        tr = 0.95f * tr + (PV);                          \
        u  = 0.9f * u + tr;                              \
        if (u > 1.0f) { cnt += 1.0f; u = 0.0f; }         \
    } while (0)

    #pragma unroll 1
    for (int t = 0; t < T_STEPS; t += 4) {
        float p0 = p[(size_t)(t + 0) * CELLS];
        float p1 = p[(size_t)(t + 1) * CELLS];
        float p2 = p[(size_t)(t + 2) * CELLS];
        float p3 = p[(size_t)(t + 3) * CELLS];
        LIF_STEP(p0); LIF_STEP(p1); LIF_STEP(p2); LIF_STEP(p3);
    }
#undef LIF_STEP
    g_counts[cell] = cnt;
}

// ---------------------------------------------------------------------------------
// Decoder: out[b,c] = sum_f counts[b,f] * dec_w[c,f] + dec_b[c]
// One block per b; warp c reduces over F.
// ---------------------------------------------------------------------------------
__global__ void decoder_kernel(const float* __restrict__ dec_w,
                               const float* __restrict__ dec_b,
                               float* __restrict__ out) {
    __shared__ float sc[NF];
    int b = blockIdx.x;
    for (int i = threadIdx.x; i < NF; i += blockDim.x) sc[i] = g_counts[b * NF + i];
    __syncthreads();
    int warp = threadIdx.x >> 5, lane = threadIdx.x & 31;
    if (warp < NC) {
        float s = 0.f;
        #pragma unroll
        for (int f = lane; f < NF; f += 32) s += sc[f] * dec_w[warp * NF + f];
        #pragma unroll
        for (int o = 16; o; o >>= 1) s += __shfl_xor_sync(0xffffffffu, s, o);
        if (lane == 0) out[b * NC + warp] = s + dec_b[warp];
    }
}

// ---------------------------------------------------------------------------------
extern "C" void kernel_launch(void* const* d_in, const int* in_sizes, int n_in,
                              void* d_out, int out_size) {
    const float* x  = (const float*)d_in[0];  // [T, B, W]
    const float* w  = (const float*)d_in[1];  // [F, W]
    const float* dw = (const float*)d_in[2];  // [C, F]
    const float* db = (const float*)d_in[3];  // [C]
    float* out = (float*)d_out;               // [B, C]

    (void)in_sizes; (void)n_in; (void)out_size;

    int xpairs = M_ROWS * WIN / 2;            // 8,192,000
    int wpairs = NF * WIN / 2;                // 65,536
    split_x_kernel<<<(xpairs + 255) / 256, 256>>>(x, xpairs);
    split_w_kernel<<<(wpairs + 255) / 256, 256>>>(w, wpairs);
    gemm_kernel<<<dim3(NF / BN, M_ROWS / BM), 256>>>();
    scan_kernel<<<CELLS / 256, 256>>>();
    decoder_kernel<<<BATCH, 320>>>(dw, db, out);
}

// round 5
// speedup vs baseline: 1.0844x; 1.0844x over previous
#include <cuda_runtime.h>
#include <cuda_bf16.h>
#include <cstdint>

// Problem constants
#define T_STEPS 500
#define BATCH   128
#define WIN     256
#define NF      512
#define NC      10
#define M_ROWS  (T_STEPS * BATCH)   // 64000
#define K3      (WIN * 3)           // 768  (extended-K bf16 split: [h,l,h] x [h,h,l])
#define CELLS   (BATCH * NF)        // 65536

// T chunking: keep proj chunk resident in L2 (32 MB << 126 MB)
#define TCHUNK  125
#define NCHUNK  (T_STEPS / TCHUNK)  // 4
#define MCHUNK  (TCHUNK * BATCH)    // 16000 rows per chunk

// GEMM tiling
#define BM 128
#define BN 128
#define BK 32
#define NKITER (K3 / BK)            // 24
#define STAGES 4
#define SKEW 8
#define LDS_ROW (BK + SKEW)         // 40 bf16 rows, conflict-free for ldmatrix
#define STAGE_A (BM * LDS_ROW)      // 5120 bf16 = 10240 B
#define STAGE_B (BN * LDS_ROW)

// -------- device scratch --------
__device__ __nv_bfloat16 g_Xs[(size_t)M_ROWS * K3];    // ~98 MB (split once)
__device__ __nv_bfloat16 g_Ws[(size_t)NF * K3];        // ~0.8 MB
__device__ float         g_proj[(size_t)MCHUNK * NF];  // 32 MB, reused per chunk (L2-resident)
__device__ float         g_u[CELLS], g_tr[CELLS], g_cnt[CELLS];

// ---------------------------------------------------------------------------------
// Split fp32 -> (hi, lo) bf16 into extended-K slots.
//   A: per k -> [h, l, h]   B: per k -> [h, h, l]  => products h*h + l*h + h*l
// ---------------------------------------------------------------------------------
__global__ void split_x_kernel(const float* __restrict__ x, int npairs) {
    int i = blockIdx.x * blockDim.x + threadIdx.x;
    if (i >= npairs) return;
    float2 v = reinterpret_cast<const float2*>(x)[i];
    __nv_bfloat16 h0 = __float2bfloat16(v.x);
    __nv_bfloat16 l0 = __float2bfloat16(v.x - __bfloat162float(h0));
    __nv_bfloat16 h1 = __float2bfloat16(v.y);
    __nv_bfloat16 l1 = __float2bfloat16(v.y - __bfloat162float(h1));
    unsigned hu0 = __bfloat16_as_ushort(h0), lu0 = __bfloat16_as_ushort(l0);
    unsigned hu1 = __bfloat16_as_ushort(h1), lu1 = __bfloat16_as_ushort(l1);
    unsigned* out = reinterpret_cast<unsigned*>(g_Xs);
    out[3 * i + 0] = hu0 | (lu0 << 16);
    out[3 * i + 1] = hu0 | (hu1 << 16);
    out[3 * i + 2] = lu1 | (hu1 << 16);
}

__global__ void split_w_kernel(const float* __restrict__ w, int npairs) {
    int i = blockIdx.x * blockDim.x + threadIdx.x;
    if (i >= npairs) return;
    float2 v = reinterpret_cast<const float2*>(w)[i];
    __nv_bfloat16 h0 = __float2bfloat16(v.x);
    __nv_bfloat16 l0 = __float2bfloat16(v.x - __bfloat162float(h0));
    __nv_bfloat16 h1 = __float2bfloat16(v.y);
    __nv_bfloat16 l1 = __float2bfloat16(v.y - __bfloat162float(h1));
    unsigned hu0 = __bfloat16_as_ushort(h0), lu0 = __bfloat16_as_ushort(l0);
    unsigned hu1 = __bfloat16_as_ushort(h1), lu1 = __bfloat16_as_ushort(l1);
    unsigned* out = reinterpret_cast<unsigned*>(g_Ws);
    out[3 * i + 0] = hu0 | (hu0 << 16);
    out[3 * i + 1] = lu0 | (hu1 << 16);
    out[3 * i + 2] = hu1 | (lu1 << 16);
}

// ---------------------------------------------------------------------------------
// GEMM chunk: proj[MCHUNK, NF] = Xs[mbase:mbase+MCHUNK, K3] * Ws^T
// CTA 128x128, 8 warps (4 m x 2 n), warp tile 32x64. 4-stage cp.async pipeline.
// ---------------------------------------------------------------------------------
__global__ void __launch_bounds__(256) gemm_kernel(int mbase) {
    extern __shared__ __align__(16) __nv_bfloat16 smem[];
    __nv_bfloat16* sAb = smem;                       // STAGES * STAGE_A
    __nv_bfloat16* sBb = smem + STAGES * STAGE_A;    // STAGES * STAGE_B

    const int tid  = threadIdx.x;
    const int bn   = blockIdx.x;     // 0..3
    const int bm   = blockIdx.y;     // 0..124
    const int warp = tid >> 5;
    const int lane = tid & 31;
    const int wm   = warp & 3;       // m offset = 32*wm
    const int wn   = warp >> 2;      // n offset = 64*wn

    float acc[2][8][4];
    #pragma unroll
    for (int mi = 0; mi < 2; mi++)
        #pragma unroll
        for (int n8 = 0; n8 < 8; n8++)
            #pragma unroll
            for (int q = 0; q < 4; q++) acc[mi][n8][q] = 0.f;

    auto load_stage = [&](int st, int kt) {
        __nv_bfloat16* sA = sAb + st * STAGE_A;
        __nv_bfloat16* sB = sBb + st * STAGE_B;
        #pragma unroll
        for (int it = 0; it < 2; it++) {
            int c = tid + it * 256;          // 0..511
            int r = c >> 2, q = c & 3;       // row, 16B chunk within k-slab
            const __nv_bfloat16* gA = &g_Xs[(size_t)(mbase + bm * BM + r) * K3 + kt * BK + q * 8];
            unsigned sa = (unsigned)__cvta_generic_to_shared(&sA[r * LDS_ROW + q * 8]);
            asm volatile("cp.async.cg.shared.global [%0], [%1], 16;\n" :: "r"(sa), "l"(gA));
            const __nv_bfloat16* gB = &g_Ws[(size_t)(bn * BN + r) * K3 + kt * BK + q * 8];
            unsigned sb = (unsigned)__cvta_generic_to_shared(&sB[r * LDS_ROW + q * 8]);
            asm volatile("cp.async.cg.shared.global [%0], [%1], 16;\n" :: "r"(sb), "l"(gB));
        }
    };

    auto compute_stage = [&](int st) {
        __nv_bfloat16* sA = sAb + st * STAGE_A;
        __nv_bfloat16* sB = sBb + st * STAGE_B;
        #pragma unroll
        for (int kk = 0; kk < BK; kk += 16) {
            unsigned af[2][4];
            #pragma unroll
            for (int mi = 0; mi < 2; mi++) {
                int row = wm * 32 + mi * 16 + (lane & 15);
                int col = kk + (lane >> 4) * 8;
                unsigned a = (unsigned)__cvta_generic_to_shared(&sA[row * LDS_ROW + col]);
                asm volatile("ldmatrix.sync.aligned.m8n8.x4.shared.b16 {%0,%1,%2,%3}, [%4];"
                             : "=r"(af[mi][0]), "=r"(af[mi][1]), "=r"(af[mi][2]), "=r"(af[mi][3])
                             : "r"(a));
            }
            unsigned bfr[4][4];
            #pragma unroll
            for (int nj = 0; nj < 4; nj++) {
                int row = wn * 64 + nj * 16 + (lane & 7) + ((lane >> 4) << 3);
                int col = kk + ((lane >> 3) & 1) * 8;
                unsigned a = (unsigned)__cvta_generic_to_shared(&sB[row * LDS_ROW + col]);
                asm volatile("ldmatrix.sync.aligned.m8n8.x4.shared.b16 {%0,%1,%2,%3}, [%4];"
                             : "=r"(bfr[nj][0]), "=r"(bfr[nj][1]), "=r"(bfr[nj][2]), "=r"(bfr[nj][3])
                             : "r"(a));
            }
            #pragma unroll
            for (int mi = 0; mi < 2; mi++) {
                #pragma unroll
                for (int n8 = 0; n8 < 8; n8++) {
                    int nj = n8 >> 1, h = (n8 & 1) * 2;
                    asm volatile(
                        "mma.sync.aligned.m16n8k16.row.col.f32.bf16.bf16.f32 "
                        "{%0,%1,%2,%3}, {%4,%5,%6,%7}, {%8,%9}, {%0,%1,%2,%3};"
                        : "+f"(acc[mi][n8][0]), "+f"(acc[mi][n8][1]),
                          "+f"(acc[mi][n8][2]), "+f"(acc[mi][n8][3])
                        : "r"(af[mi][0]), "r"(af[mi][1]), "r"(af[mi][2]), "r"(af[mi][3]),
                          "r"(bfr[nj][h]), "r"(bfr[nj][h + 1]));
                }
            }
        }
    };

    // Prologue: fill STAGES-1 stages
    #pragma unroll
    for (int s = 0; s < STAGES - 1; s++) {
        load_stage(s, s);
        asm volatile("cp.async.commit_group;");
    }

    for (int kt = 0; kt < NKITER; kt++) {
        asm volatile("cp.async.wait_group %0;" :: "n"(STAGES - 2));
        __syncthreads();   // stage kt visible to all; all warps done computing stage (kt-1)
        if (kt + STAGES - 1 < NKITER)
            load_stage((kt + STAGES - 1) % STAGES, kt + STAGES - 1);
        asm volatile("cp.async.commit_group;");   // unconditional: keeps group accounting uniform
        compute_stage(kt % STAGES);
    }

    // Epilogue: accumulators -> g_proj (chunk-local rows)
    #pragma unroll
    for (int mi = 0; mi < 2; mi++) {
        #pragma unroll
        for (int n8 = 0; n8 < 8; n8++) {
            int grow = bm * BM + wm * 32 + mi * 16 + (lane >> 2);
            int gcol = bn * BN + wn * 64 + n8 * 8 + (lane & 3) * 2;
            float2* p0 = reinterpret_cast<float2*>(&g_proj[(size_t)grow * NF + gcol]);
            *p0 = make_float2(acc[mi][n8][0], acc[mi][n8][1]);
            float2* p1 = reinterpret_cast<float2*>(&g_proj[(size_t)(grow + 8) * NF + gcol]);
            *p1 = make_float2(acc[mi][n8][2], acc[mi][n8][3]);
        }
    }
}

// ---------------------------------------------------------------------------------
// LIF scan over one T-chunk (125 steps). proj chunk is L2-resident.
// One thread per (b, f) cell; state carried in global between chunks.
// ---------------------------------------------------------------------------------
__global__ void scan_chunk_kernel(int chunk) {
    int cell = blockIdx.x * blockDim.x + threadIdx.x;
    float u, tr, cnt;
    if (chunk == 0) { u = 0.f; tr = 0.f; cnt = 0.f; }
    else { u = g_u[cell]; tr = g_tr[cell]; cnt = g_cnt[cell]; }

    const float* p = g_proj + cell;

#define LIF_STEP(PV)                                     \
    do {                                                 \
        tr = 0.95f * tr + (PV);                          \
        u  = 0.9f * u + tr;                              \
        if (u > 1.0f) { cnt += 1.0f; u = 0.0f; }         \
    } while (0)

    #pragma unroll 1
    for (int t = 0; t < TCHUNK; t += 5) {
        float p0 = p[(size_t)(t + 0) * CELLS];
        float p1 = p[(size_t)(t + 1) * CELLS];
        float p2 = p[(size_t)(t + 2) * CELLS];
        float p3 = p[(size_t)(t + 3) * CELLS];
        float p4 = p[(size_t)(t + 4) * CELLS];
        LIF_STEP(p0); LIF_STEP(p1); LIF_STEP(p2); LIF_STEP(p3); LIF_STEP(p4);
    }
#undef LIF_STEP

    g_u[cell] = u; g_tr[cell] = tr; g_cnt[cell] = cnt;
}

// ---------------------------------------------------------------------------------
// Decoder: out[b,c] = sum_f cnt[b,f] * dec_w[c,f] + dec_b[c]
// ---------------------------------------------------------------------------------
__global__ void decoder_kernel(const float* __restrict__ dec_w,
                               const float* __restrict__ dec_b,
                               float* __restrict__ out) {
    __shared__ float sc[NF];
    int b = blockIdx.x;
    for (int i = threadIdx.x; i < NF; i += blockDim.x) sc[i] = g_cnt[b * NF + i];
    __syncthreads();
    int warp = threadIdx.x >> 5, lane = threadIdx.x & 31;
    if (warp < NC) {
        float s = 0.f;
        #pragma unroll
        for (int f = lane; f < NF; f += 32) s += sc[f] * dec_w[warp * NF + f];
        #pragma unroll
        for (int o = 16; o; o >>= 1) s += __shfl_xor_sync(0xffffffffu, s, o);
        if (lane == 0) out[b * NC + warp] = s + dec_b[warp];
    }
}

// ---------------------------------------------------------------------------------
extern "C" void kernel_launch(void* const* d_in, const int* in_sizes, int n_in,
                              void* d_out, int out_size) {
    const float* x  = (const float*)d_in[0];  // [T, B, W]
    const float* w  = (const float*)d_in[1];  // [F, W]
    const float* dw = (const float*)d_in[2];  // [C, F]
    const float* db = (const float*)d_in[3];  // [C]
    float* out = (float*)d_out;               // [B, C]
    (void)in_sizes; (void)n_in; (void)out_size;

    // Unconditional (no static guards allowed). Not stream-ordered; idempotent.
    const int smem_bytes = STAGES * (STAGE_A + STAGE_B) * (int)sizeof(__nv_bfloat16); // 81920
    cudaFuncSetAttribute(gemm_kernel, cudaFuncAttributeMaxDynamicSharedMemorySize, smem_bytes);

    int xpairs = M_ROWS * WIN / 2;            // 8,192,000
    int wpairs = NF * WIN / 2;                // 65,536
    split_x_kernel<<<(xpairs + 255) / 256, 256>>>(x, xpairs);
    split_w_kernel<<<(wpairs + 255) / 256, 256>>>(w, wpairs);

    for (int c = 0; c < NCHUNK; c++) {
        gemm_kernel<<<dim3(NF / BN, MCHUNK / BM), 256, smem_bytes>>>(c * MCHUNK);
        scan_chunk_kernel<<<CELLS / 256, 256>>>(c);
    }
    decoder_kernel<<<BATCH, 320>>>(dw, db, out);
}